// round 8
// baseline (speedup 1.0000x reference)
#include <cuda_runtime.h>
#include <math.h>
#include <stdint.h>

// Problem constants
#define BB 4
#define SS 1024
#define DD 1024
#define HH 16
#define HD 64
#define NEG_V 10000.0f

// Scratch (static device arrays; no allocation allowed)
__device__ float g_qkv[BB * SS * 3 * DD];   // [4096,3072] tf32-rounded
__device__ float g_am[BB * SS * DD];        // [4096,1024] tf32-rounded
__device__ float g_xtf[BB * SS * DD];       // x converted to tf32 bits
__device__ float g_watf[DD * 3 * DD];       // w_attn converted
__device__ float g_wptf[DD * DD];           // w_proj converted
__device__ float2 g_part[BB * HH * 8 * SS]; // per (z, colblock, row): (max, sumexp)

// ---------------------------------------------------------------------------
// helpers
// ---------------------------------------------------------------------------
__device__ __forceinline__ uint32_t f2tf(float f) {
    uint32_t u;
    asm("cvt.rna.tf32.f32 %0, %1;" : "=r"(u) : "f"(f));
    return u;
}

__device__ __forceinline__ void mma8(float* c, const uint32_t* a, const uint32_t* b) {
    asm volatile(
        "mma.sync.aligned.m16n8k8.row.col.f32.tf32.tf32.f32 "
        "{%0,%1,%2,%3}, {%4,%5,%6,%7}, {%8,%9}, {%0,%1,%2,%3};\n"
        : "+f"(c[0]), "+f"(c[1]), "+f"(c[2]), "+f"(c[3])
        : "r"(a[0]), "r"(a[1]), "r"(a[2]), "r"(a[3]), "r"(b[0]), "r"(b[1]));
}

__device__ __forceinline__ void cp16(uint32_t dst, const void* src) {
    asm volatile("cp.async.cg.shared.global [%0], [%1], 16;\n" :: "r"(dst), "l"(src));
}
#define CP_COMMIT() asm volatile("cp.async.commit_group;\n" ::: "memory")
#define CP_WAIT(N)  asm volatile("cp.async.wait_group %0;\n" :: "n"(N) : "memory")

// m16n8k8 fragment maps (row.col):
//  A(16x8):  a0=A[g][t] a1=A[g+8][t] a2=A[g][t+4] a3=A[g+8][t+4]  (g=lane>>2,t=lane&3)
//  B(8x8):   b0=B[t][g] b1=B[t+4][g]
//  C(16x8):  c0=C[g][2t] c1=C[g][2t+1] c2=C[g+8][2t] c3=C[g+8][2t+1]

// ---------------------------------------------------------------------------
// Elementwise tf32 pre-convert (n multiple of 1024)
// ---------------------------------------------------------------------------
__global__ __launch_bounds__(256) void cvt_tf32(
    const float* __restrict__ src, float* __restrict__ dst)
{
    int i = (blockIdx.x * 256 + threadIdx.x) * 4;
    float4 v = *reinterpret_cast<const float4*>(src + i);
    uint4 o;
    o.x = f2tf(v.x); o.y = f2tf(v.y); o.z = f2tf(v.z); o.w = f2tf(v.w);
    *reinterpret_cast<uint4*>(dst + i) = o;
}

// ---------------------------------------------------------------------------
// Generic tf32 GEMM on pre-converted inputs: C[M,N] = A@B + bias
// BM=128 BN=128 BK=32, 256 thr (8 warps, warp 32x64), 3-stage cp.async ring.
// smem: As[3][128][36] + Bs[3][32][136] (uint32) = 107520 B
// Strides 36 (36r%32=4r) / 136 (136k%32=8k): bank-partitioned scalar LDS.
// ---------------------------------------------------------------------------
#define GA_ST 36
#define GB_ST 136
#define GA_SZ (128 * GA_ST)   // 4608
#define GB_SZ (32 * GB_ST)    // 4352
#define G_SMEM ((3 * (GA_SZ + GB_SZ)) * 4)

template<bool ROUND>
__global__ __launch_bounds__(256, 2) void gemm_tc(
    const float* __restrict__ A, const float* __restrict__ B,
    const float* __restrict__ bias, float* __restrict__ C,
    int K, int lda, int ldb, int ldc)
{
    extern __shared__ __align__(16) uint32_t sm[];
    uint32_t* As = sm;
    uint32_t* Bs = sm + 3 * GA_SZ;
    const uint32_t smb = (uint32_t)__cvta_generic_to_shared(sm);

    const int tid = threadIdx.x, lane = tid & 31, warp = tid >> 5;
    const int wm = warp & 3, wn = warp >> 2;
    const int rowStart = blockIdx.y * 128, colStart = blockIdx.x * 128;

    float acc[2][8][4];
#pragma unroll
    for (int mi = 0; mi < 2; mi++)
#pragma unroll
        for (int ni = 0; ni < 8; ni++)
#pragma unroll
            for (int r = 0; r < 4; r++) acc[mi][ni][r] = 0.f;

#define G_LOAD(KB0, s) do {                                                      \
    _Pragma("unroll")                                                            \
    for (int i = 0; i < 4; i++) {                                                \
        int v = tid * 4 + i;                                                     \
        int r = v >> 3, c4 = (v & 7) << 2;                                       \
        cp16(smb + ((s) * GA_SZ + r * GA_ST + c4) * 4,                           \
             &A[(size_t)(rowStart + r) * lda + (KB0) + c4]);                     \
    }                                                                            \
    _Pragma("unroll")                                                            \
    for (int i = 0; i < 4; i++) {                                                \
        int v = tid + i * 256;                                                   \
        int r = v >> 5, c4 = (v & 31) << 2;                                      \
        cp16(smb + (3 * GA_SZ + (s) * GB_SZ + r * GB_ST + c4) * 4,               \
             &B[(size_t)((KB0) + r) * ldb + colStart + c4]);                     \
    } } while (0)

#define G_COMP(s) do {                                                           \
    const uint32_t* Av = As + (s) * GA_SZ;                                       \
    const uint32_t* Bv = Bs + (s) * GB_SZ;                                       \
    _Pragma("unroll")                                                            \
    for (int ks = 0; ks < 4; ks++) {                                             \
        uint32_t af[2][4];                                                       \
        _Pragma("unroll")                                                        \
        for (int mi = 0; mi < 2; mi++) {                                         \
            int r = wm * 32 + mi * 16 + (lane >> 2);                             \
            int cc = ks * 8 + (lane & 3);                                        \
            af[mi][0] = Av[r * GA_ST + cc];                                      \
            af[mi][1] = Av[(r + 8) * GA_ST + cc];                                \
            af[mi][2] = Av[r * GA_ST + cc + 4];                                  \
            af[mi][3] = Av[(r + 8) * GA_ST + cc + 4];                            \
        }                                                                        \
        _Pragma("unroll")                                                        \
        for (int ni = 0; ni < 8; ni++) {                                         \
            int n = wn * 64 + ni * 8 + (lane >> 2);                              \
            uint32_t bf[2];                                                      \
            bf[0] = Bv[(ks * 8 + (lane & 3)) * GB_ST + n];                       \
            bf[1] = Bv[(ks * 8 + 4 + (lane & 3)) * GB_ST + n];                   \
            mma8(acc[0][ni], af[0], bf);                                         \
            mma8(acc[1][ni], af[1], bf);                                         \
        }                                                                        \
    } } while (0)

    const int NC = K / 32;
    G_LOAD(0, 0); CP_COMMIT();
    G_LOAD(32, 1); CP_COMMIT();
    int st = 0;
    for (int c = 0; c < NC; c++) {
        CP_WAIT(1);
        __syncthreads();
        G_COMP(st);
        int s2 = st + 2; if (s2 >= 3) s2 -= 3;
        if (c + 2 < NC) G_LOAD((c + 2) * 32, s2);
        CP_COMMIT();
        st++; if (st >= 3) st = 0;
    }

#pragma unroll
    for (int mi = 0; mi < 2; mi++)
#pragma unroll
        for (int ni = 0; ni < 8; ni++) {
            int row = rowStart + wm * 32 + mi * 16 + (lane >> 2);
            int col = colStart + wn * 64 + ni * 8 + (lane & 3) * 2;
            float b0 = bias[col], b1 = bias[col + 1];
            float v00 = acc[mi][ni][0] + b0, v01 = acc[mi][ni][1] + b1;
            float v10 = acc[mi][ni][2] + b0, v11 = acc[mi][ni][3] + b1;
            if (ROUND) {
                C[(size_t)row * ldc + col]           = __uint_as_float(f2tf(v00));
                C[(size_t)row * ldc + col + 1]       = __uint_as_float(f2tf(v01));
                C[(size_t)(row + 8) * ldc + col]     = __uint_as_float(f2tf(v10));
                C[(size_t)(row + 8) * ldc + col + 1] = __uint_as_float(f2tf(v11));
            } else {
                C[(size_t)row * ldc + col]           = v00;
                C[(size_t)row * ldc + col + 1]       = v01;
                C[(size_t)(row + 8) * ldc + col]     = v10;
                C[(size_t)(row + 8) * ldc + col + 1] = v11;
            }
        }
}

// ---------------------------------------------------------------------------
// QK^T: per z, 128x128 tile, K=64 single-shot. Writes raw masked scores to
// Wout AND per-(row, colblock) (max, sumexp) partials to g_part.
// smem: Qs[128][68] + Ks[128][68] = 69632 B.
// ---------------------------------------------------------------------------
#define QK_ST 68
#define QK_SZ (128 * QK_ST)
#define QK_SMEM (2 * QK_SZ * 4)

__global__ __launch_bounds__(256, 2) void qk_tc(
    const float* __restrict__ qkv, const float* __restrict__ mask,
    float* __restrict__ Wout)
{
    extern __shared__ __align__(16) uint32_t sm[];
    __shared__ float2 sstat[128][2];
    uint32_t* Qs = sm;
    uint32_t* Ks = sm + QK_SZ;
    const uint32_t smb = (uint32_t)__cvta_generic_to_shared(sm);

    const int tid = threadIdx.x, lane = tid & 31, warp = tid >> 5;
    const int wm = warp & 3, wn = warp >> 2;
    const int rowStart = blockIdx.y * 128, colStart = blockIdx.x * 128;
    const int z = blockIdx.z, b = z >> 4, h = z & 15;

    const float* Qb = qkv + (size_t)b * SS * 3 * DD + h * HD;
    const float* Kb = Qb + DD;

#pragma unroll
    for (int i = 0; i < 8; i++) {
        int v = tid + i * 256;
        int r = v >> 4, c4 = (v & 15) << 2;
        cp16(smb + (r * QK_ST + c4) * 4,
             &Qb[(size_t)(rowStart + r) * (3 * DD) + c4]);
        cp16(smb + (QK_SZ + r * QK_ST + c4) * 4,
             &Kb[(size_t)(colStart + r) * (3 * DD) + c4]);
    }
    CP_COMMIT();

    float acc[2][8][4];
#pragma unroll
    for (int mi = 0; mi < 2; mi++)
#pragma unroll
        for (int ni = 0; ni < 8; ni++)
#pragma unroll
            for (int r = 0; r < 4; r++) acc[mi][ni][r] = 0.f;

    CP_WAIT(0);
    __syncthreads();

#pragma unroll
    for (int ks = 0; ks < 8; ks++) {
        uint32_t af[2][4];
#pragma unroll
        for (int mi = 0; mi < 2; mi++) {
            int r = wm * 32 + mi * 16 + (lane >> 2);
            int cc = ks * 8 + (lane & 3);
            af[mi][0] = Qs[r * QK_ST + cc];
            af[mi][1] = Qs[(r + 8) * QK_ST + cc];
            af[mi][2] = Qs[r * QK_ST + cc + 4];
            af[mi][3] = Qs[(r + 8) * QK_ST + cc + 4];
        }
#pragma unroll
        for (int ni = 0; ni < 8; ni++) {
            int n = wn * 64 + ni * 8 + (lane >> 2);
            uint32_t bf[2];
            bf[0] = Ks[n * QK_ST + ks * 8 + (lane & 3)];
            bf[1] = Ks[n * QK_ST + ks * 8 + 4 + (lane & 3)];
            mma8(acc[0][ni], af[0], bf);
            mma8(acc[1][ni], af[1], bf);
        }
    }

    // epilogue: finalize values (scale+causal+mask) in acc, write raw scores
    const float* mrow = mask + (size_t)b * SS;
#pragma unroll
    for (int mi = 0; mi < 2; mi++)
#pragma unroll
        for (int ni = 0; ni < 8; ni++) {
            int row0 = rowStart + wm * 32 + mi * 16 + (lane >> 2);
            int col = colStart + wn * 64 + ni * 8 + (lane & 3) * 2;
            float m0 = mrow[col], m1 = mrow[col + 1];
#pragma unroll
            for (int half = 0; half < 2; half++) {
                int row = row0 + half * 8;
                float v0 = ((row >= col)     ? acc[mi][ni][half * 2 + 0] * 0.125f : -NEG_V) + m0;
                float v1 = ((row >= col + 1) ? acc[mi][ni][half * 2 + 1] * 0.125f : -NEG_V) + m1;
                acc[mi][ni][half * 2 + 0] = v0;
                acc[mi][ni][half * 2 + 1] = v1;
                float* crow = &Wout[((size_t)z * SS + row) * SS + col];
                crow[0] = v0;
                crow[1] = v1;
            }
        }

    // per-row block stats over the 128-col tile
    float rmax[2][2], rsum[2][2];
#pragma unroll
    for (int mi = 0; mi < 2; mi++)
#pragma unroll
        for (int half = 0; half < 2; half++) rmax[mi][half] = -1e30f;
#pragma unroll
    for (int mi = 0; mi < 2; mi++)
#pragma unroll
        for (int ni = 0; ni < 8; ni++)
#pragma unroll
            for (int half = 0; half < 2; half++)
                rmax[mi][half] = fmaxf(rmax[mi][half],
                    fmaxf(acc[mi][ni][half * 2], acc[mi][ni][half * 2 + 1]));
#pragma unroll
    for (int o = 1; o <= 2; o <<= 1)
#pragma unroll
        for (int mi = 0; mi < 2; mi++)
#pragma unroll
            for (int half = 0; half < 2; half++)
                rmax[mi][half] = fmaxf(rmax[mi][half],
                    __shfl_xor_sync(0xffffffffu, rmax[mi][half], o));
#pragma unroll
    for (int mi = 0; mi < 2; mi++)
#pragma unroll
        for (int half = 0; half < 2; half++) rsum[mi][half] = 0.f;
#pragma unroll
    for (int mi = 0; mi < 2; mi++)
#pragma unroll
        for (int ni = 0; ni < 8; ni++)
#pragma unroll
            for (int half = 0; half < 2; half++)
                rsum[mi][half] += __expf(acc[mi][ni][half * 2]     - rmax[mi][half])
                                + __expf(acc[mi][ni][half * 2 + 1] - rmax[mi][half]);
#pragma unroll
    for (int o = 1; o <= 2; o <<= 1)
#pragma unroll
        for (int mi = 0; mi < 2; mi++)
#pragma unroll
            for (int half = 0; half < 2; half++)
                rsum[mi][half] += __shfl_xor_sync(0xffffffffu, rsum[mi][half], o);

    if ((lane & 3) == 0) {
#pragma unroll
        for (int mi = 0; mi < 2; mi++)
#pragma unroll
            for (int half = 0; half < 2; half++) {
                int rl = wm * 32 + mi * 16 + (lane >> 2) + half * 8;
                sstat[rl][wn] = make_float2(rmax[mi][half], rsum[mi][half]);
            }
    }
    __syncthreads();
    if (tid < 128) {
        float2 p0 = sstat[tid][0], p1 = sstat[tid][1];
        float m = fmaxf(p0.x, p1.x);
        float s = p0.y * __expf(p0.x - m) + p1.y * __expf(p1.x - m);
        g_part[((size_t)z * 8 + blockIdx.x) * SS + rowStart + tid] = make_float2(m, s);
    }
}

// ---------------------------------------------------------------------------
// AV: per z, O[1024,64] = softmax(S)@V. Reads RAW scores from W (in w_out),
// normalizes on the fly (stats from g_part), overwrites w_out with probs
// in place, accumulates O via mma. BM=128 BN=64 BK=32, 3-stage ring.
// smem: As[3][128][36] + Bs[3][32][72] = 82944 B.
// ---------------------------------------------------------------------------
#define VA_ST 36
#define VB_ST 72
#define VA_SZ (128 * VA_ST)   // 4608
#define VB_SZ (32 * VB_ST)    // 2304
#define V_SMEM ((3 * (VA_SZ + VB_SZ)) * 4)

__global__ __launch_bounds__(256, 2) void av_tc(
    float* __restrict__ W, const float* __restrict__ qkv,
    float* __restrict__ Am)
{
    extern __shared__ __align__(16) uint32_t sm[];
    __shared__ float2 sstat[128];
    uint32_t* As = sm;
    uint32_t* Bs = sm + 3 * VA_SZ;
    const uint32_t smb = (uint32_t)__cvta_generic_to_shared(sm);

    const int tid = threadIdx.x, lane = tid & 31, warp = tid >> 5;
    const int rowStart = blockIdx.x * 128;
    const int z = blockIdx.y, b = z >> 4, h = z & 15;

    float* Wb = W + (size_t)z * SS * SS;
    const float* Vb = qkv + (size_t)b * SS * 3 * DD + 2 * DD + h * HD;

    float acc[8][4];
#pragma unroll
    for (int ni = 0; ni < 8; ni++)
#pragma unroll
        for (int r = 0; r < 4; r++) acc[ni][r] = 0.f;

#define V_LOAD(KB0, s) do {                                                      \
    _Pragma("unroll")                                                            \
    for (int i = 0; i < 4; i++) {                                                \
        int v = tid + i * 256;                                                   \
        int r = v >> 3, c4 = (v & 7) << 2;                                       \
        cp16(smb + ((s) * VA_SZ + r * VA_ST + c4) * 4,                           \
             &Wb[(size_t)(rowStart + r) * SS + (KB0) + c4]);                     \
    }                                                                            \
    _Pragma("unroll")                                                            \
    for (int i = 0; i < 2; i++) {                                                \
        int v = tid * 2 + i;                                                     \
        int r = v >> 4, c4 = (v & 15) << 2;                                      \
        cp16(smb + (3 * VA_SZ + (s) * VB_SZ + r * VB_ST + c4) * 4,               \
             &Vb[(size_t)((KB0) + r) * (3 * DD) + c4]);                          \
    } } while (0)

    V_LOAD(0, 0); CP_COMMIT();
    V_LOAD(32, 1); CP_COMMIT();

    // combine per-block stats -> per-row (max, 1/sum)
    if (tid < 128) {
        int row = rowStart + tid;
        float m = -1e30f;
        float2 pp[8];
#pragma unroll
        for (int cb = 0; cb < 8; cb++) {
            pp[cb] = g_part[((size_t)z * 8 + cb) * SS + row];
            m = fmaxf(m, pp[cb].x);
        }
        float s = 0.f;
#pragma unroll
        for (int cb = 0; cb < 8; cb++) s += pp[cb].y * __expf(pp[cb].x - m);
        sstat[tid] = make_float2(m, 1.0f / s);
    }
    __syncthreads();

    const int rl0 = warp * 16 + (lane >> 2);
    const float2 st0 = sstat[rl0];
    const float2 st1 = sstat[rl0 + 8];
    float* wr0 = &Wb[(size_t)(rowStart + rl0) * SS];
    float* wr1 = &Wb[(size_t)(rowStart + rl0 + 8) * SS];

// NOTE: macro-local vars use 'cc' to avoid capturing the caller's loop
// variable through the KB0 text substitution (round-7 bug).
#define V_COMP(s, KB0) do {                                                      \
    const uint32_t* Av = As + (s) * VA_SZ;                                       \
    const uint32_t* Bv = Bs + (s) * VB_SZ;                                       \
    _Pragma("unroll")                                                            \
    for (int ks = 0; ks < 4; ks++) {                                             \
        int cc = ks * 8 + (lane & 3);                                            \
        uint32_t af[4];                                                          \
        float p0 = __expf(__uint_as_float(Av[rl0 * VA_ST + cc])       - st0.x) * st0.y; \
        float p1 = __expf(__uint_as_float(Av[(rl0 + 8) * VA_ST + cc]) - st1.x) * st1.y; \
        float p2 = __expf(__uint_as_float(Av[rl0 * VA_ST + cc + 4])       - st0.x) * st0.y; \
        float p3 = __expf(__uint_as_float(Av[(rl0 + 8) * VA_ST + cc + 4]) - st1.x) * st1.y; \
        wr0[(KB0) + cc]     = p0;                                                \
        wr1[(KB0) + cc]     = p1;                                                \
        wr0[(KB0) + cc + 4] = p2;                                                \
        wr1[(KB0) + cc + 4] = p3;                                                \
        af[0] = f2tf(p0); af[1] = f2tf(p1); af[2] = f2tf(p2); af[3] = f2tf(p3);  \
        _Pragma("unroll")                                                        \
        for (int ni = 0; ni < 8; ni++) {                                         \
            int n = ni * 8 + (lane >> 2);                                        \
            uint32_t bf[2];                                                      \
            bf[0] = Bv[(ks * 8 + (lane & 3)) * VB_ST + n];                       \
            bf[1] = Bv[(ks * 8 + 4 + (lane & 3)) * VB_ST + n];                   \
            mma8(acc[ni], af, bf);                                               \
        }                                                                        \
    } } while (0)

    const int NC = SS / 32;   // 32 chunks
    int st = 0;
    for (int c = 0; c < NC; c++) {
        CP_WAIT(1);
        __syncthreads();
        V_COMP(st, c * 32);
        int s2 = st + 2; if (s2 >= 3) s2 -= 3;
        if (c + 2 < NC) V_LOAD((c + 2) * 32, s2);
        CP_COMMIT();
        st++; if (st >= 3) st = 0;
    }

#pragma unroll
    for (int ni = 0; ni < 8; ni++) {
        int row = rowStart + warp * 16 + (lane >> 2);
        int col = h * HD + ni * 8 + (lane & 3) * 2;
        float* o0 = &Am[((size_t)b * SS + row) * DD + col];
        float* o1 = &Am[((size_t)b * SS + row + 8) * DD + col];
        o0[0] = __uint_as_float(f2tf(acc[ni][0]));
        o0[1] = __uint_as_float(f2tf(acc[ni][1]));
        o1[0] = __uint_as_float(f2tf(acc[ni][2]));
        o1[1] = __uint_as_float(f2tf(acc[ni][3]));
    }
}

// ---------------------------------------------------------------------------
extern "C" void kernel_launch(void* const* d_in, const int* in_sizes, int n_in,
                              void* d_out, int out_size)
{
    const float* x      = (const float*)d_in[0];   // [4,1024,1024]
    const float* mask   = (const float*)d_in[1];   // [4,1,1,1024]
    const float* w_attn = (const float*)d_in[2];   // [1024,3072]
    const float* b_attn = (const float*)d_in[3];   // [1,3072]
    const float* w_proj = (const float*)d_in[4];   // [1024,1024]
    const float* b_proj = (const float*)d_in[5];   // [1,1024]

    float* out = (float*)d_out;
    float* a_out = out;                                  // [4,1024,1024]
    float* w_out = out + (size_t)BB * SS * DD;           // [4,16,1024,1024]

    float *qkv, *am, *xtf, *watf, *wptf;
    cudaGetSymbolAddress((void**)&qkv, g_qkv);
    cudaGetSymbolAddress((void**)&am, g_am);
    cudaGetSymbolAddress((void**)&xtf, g_xtf);
    cudaGetSymbolAddress((void**)&watf, g_watf);
    cudaGetSymbolAddress((void**)&wptf, g_wptf);

    cudaFuncSetAttribute(gemm_tc<true>,
                         cudaFuncAttributeMaxDynamicSharedMemorySize, G_SMEM);
    cudaFuncSetAttribute(gemm_tc<false>,
                         cudaFuncAttributeMaxDynamicSharedMemorySize, G_SMEM);
    cudaFuncSetAttribute(qk_tc,
                         cudaFuncAttributeMaxDynamicSharedMemorySize, QK_SMEM);
    cudaFuncSetAttribute(av_tc,
                         cudaFuncAttributeMaxDynamicSharedMemorySize, V_SMEM);

    // 0) pre-convert inputs to tf32 bit patterns
    cvt_tf32<<<(BB * SS * DD) / 1024, 256>>>(x, xtf);
    cvt_tf32<<<(DD * 3 * DD) / 1024, 256>>>(w_attn, watf);
    cvt_tf32<<<(DD * DD) / 1024, 256>>>(w_proj, wptf);

    // 1) qkv = x @ w_attn + b_attn (rounded to tf32 on write)
    {
        dim3 grid(3 * DD / 128, BB * SS / 128);
        gemm_tc<true><<<grid, 256, G_SMEM>>>(xtf, watf, b_attn, qkv,
                                             DD, DD, 3 * DD, 3 * DD);
    }
    // 2) raw scores + per-block softmax partials
    {
        dim3 grid(SS / 128, SS / 128, BB * HH);
        qk_tc<<<grid, 256, QK_SMEM>>>(qkv, mask, w_out);
    }
    // 3) AV with in-flight softmax normalize; overwrites w_out with probs
    {
        dim3 grid(SS / 128, BB * HH);
        av_tc<<<grid, 256, V_SMEM>>>(w_out, qkv, am);
    }
    // 4) a = am @ w_proj + b_proj -> a_out (exact)
    {
        dim3 grid(DD / 128, BB * SS / 128);
        gemm_tc<false><<<grid, 256, G_SMEM>>>(am, wptf, b_proj, a_out,
                                              DD, DD, DD, DD);
    }
}

// round 9
// speedup vs baseline: 1.4996x; 1.4996x over previous
#include <cuda_runtime.h>
#include <math.h>
#include <stdint.h>

// Problem constants
#define BB 4
#define SS 1024
#define DD 1024
#define HH 16
#define HD 64
#define NEG_V 10000.0f

// Scratch (static device arrays; no allocation allowed)
__device__ float g_qkv[BB * SS * 3 * DD];   // [4096,3072] tf32-rounded
__device__ float g_am[BB * SS * DD];        // [4096,1024] tf32-rounded
__device__ float g_xtf[BB * SS * DD];       // x converted to tf32 bits
__device__ float g_watf[DD * 3 * DD];       // w_attn converted
__device__ float g_wptf[DD * DD];           // w_proj converted

// ---------------------------------------------------------------------------
// helpers
// ---------------------------------------------------------------------------
__device__ __forceinline__ uint32_t f2tf(float f) {
    uint32_t u;
    asm("cvt.rna.tf32.f32 %0, %1;" : "=r"(u) : "f"(f));
    return u;
}

__device__ __forceinline__ void mma8(float* c, const uint32_t* a, const uint32_t* b) {
    asm volatile(
        "mma.sync.aligned.m16n8k8.row.col.f32.tf32.tf32.f32 "
        "{%0,%1,%2,%3}, {%4,%5,%6,%7}, {%8,%9}, {%0,%1,%2,%3};\n"
        : "+f"(c[0]), "+f"(c[1]), "+f"(c[2]), "+f"(c[3])
        : "r"(a[0]), "r"(a[1]), "r"(a[2]), "r"(a[3]), "r"(b[0]), "r"(b[1]));
}

__device__ __forceinline__ void cp16(uint32_t dst, const void* src) {
    asm volatile("cp.async.cg.shared.global [%0], [%1], 16;\n" :: "r"(dst), "l"(src));
}
#define CP_COMMIT() asm volatile("cp.async.commit_group;\n" ::: "memory")
#define CP_WAIT(N)  asm volatile("cp.async.wait_group %0;\n" :: "n"(N) : "memory")

// m16n8k8 fragment maps (row.col):
//  A(16x8):  a0=A[g][t] a1=A[g+8][t] a2=A[g][t+4] a3=A[g+8][t+4]  (g=lane>>2,t=lane&3)
//  B(8x8):   b0=B[t][g] b1=B[t+4][g]
//  C(16x8):  c0=C[g][2t] c1=C[g][2t+1] c2=C[g+8][2t] c3=C[g+8][2t+1]

// ---------------------------------------------------------------------------
// Elementwise tf32 pre-convert (n multiple of 1024)
// ---------------------------------------------------------------------------
__global__ __launch_bounds__(256) void cvt_tf32(
    const float* __restrict__ src, float* __restrict__ dst)
{
    int i = (blockIdx.x * 256 + threadIdx.x) * 4;
    float4 v = *reinterpret_cast<const float4*>(src + i);
    uint4 o;
    o.x = f2tf(v.x); o.y = f2tf(v.y); o.z = f2tf(v.z); o.w = f2tf(v.w);
    *reinterpret_cast<uint4*>(dst + i) = o;
}

// ---------------------------------------------------------------------------
// Generic tf32 GEMM on pre-converted inputs: C[M,N] = A@B + bias
// BM=128 BN=128 BK=16, 256 thr (8 warps, warp 32x64), 4-stage cp.async ring.
// smem: As[4][128][20] + Bs[4][16][136] (uint32) = 75776 B
// A-gather stride 20 (20r%32=4r) and B-gather stride 136 (136k%32=8k):
// perfectly bank-partitioned scalar LDS.
// ---------------------------------------------------------------------------
#define GA_ST 20
#define GB_ST 136
#define GA_SZ (128 * GA_ST)   // 2560
#define GB_SZ (16 * GB_ST)    // 2176
#define G_SMEM ((4 * (GA_SZ + GB_SZ)) * 4)

template<bool ROUND>
__global__ __launch_bounds__(256, 2) void gemm_tc(
    const float* __restrict__ A, const float* __restrict__ B,
    const float* __restrict__ bias, float* __restrict__ C,
    int K, int lda, int ldb, int ldc)
{
    extern __shared__ __align__(16) uint32_t sm[];
    uint32_t* As = sm;
    uint32_t* Bs = sm + 4 * GA_SZ;
    const uint32_t smb = (uint32_t)__cvta_generic_to_shared(sm);

    const int tid = threadIdx.x, lane = tid & 31, warp = tid >> 5;
    const int wm = warp & 3, wn = warp >> 2;
    const int rowStart = blockIdx.y * 128, colStart = blockIdx.x * 128;

    float acc[2][8][4];
#pragma unroll
    for (int mi = 0; mi < 2; mi++)
#pragma unroll
        for (int ni = 0; ni < 8; ni++)
#pragma unroll
            for (int r = 0; r < 4; r++) acc[mi][ni][r] = 0.f;

#define G_LOAD(KB0, s) do {                                                      \
    _Pragma("unroll")                                                            \
    for (int i = 0; i < 2; i++) {                                                \
        int v = tid * 2 + i;                                                     \
        int r = v >> 2, c4 = (v & 3) << 2;                                       \
        cp16(smb + ((s) * GA_SZ + r * GA_ST + c4) * 4,                           \
             &A[(size_t)(rowStart + r) * lda + (KB0) + c4]);                     \
    }                                                                            \
    _Pragma("unroll")                                                            \
    for (int i = 0; i < 2; i++) {                                                \
        int v = tid * 2 + i;                                                     \
        int r = v >> 5, c4 = (v & 31) << 2;                                      \
        cp16(smb + (4 * GA_SZ + (s) * GB_SZ + r * GB_ST + c4) * 4,               \
             &B[(size_t)((KB0) + r) * ldb + colStart + c4]);                     \
    } } while (0)

#define G_COMP(s) do {                                                           \
    const uint32_t* Av = As + (s) * GA_SZ;                                       \
    const uint32_t* Bv = Bs + (s) * GB_SZ;                                       \
    _Pragma("unroll")                                                            \
    for (int ks = 0; ks < 2; ks++) {                                             \
        uint32_t af[2][4];                                                       \
        _Pragma("unroll")                                                        \
        for (int mi = 0; mi < 2; mi++) {                                         \
            int r = wm * 32 + mi * 16 + (lane >> 2);                             \
            int cc = ks * 8 + (lane & 3);                                        \
            af[mi][0] = Av[r * GA_ST + cc];                                      \
            af[mi][1] = Av[(r + 8) * GA_ST + cc];                                \
            af[mi][2] = Av[r * GA_ST + cc + 4];                                  \
            af[mi][3] = Av[(r + 8) * GA_ST + cc + 4];                            \
        }                                                                        \
        _Pragma("unroll")                                                        \
        for (int ni = 0; ni < 8; ni++) {                                         \
            int n = wn * 64 + ni * 8 + (lane >> 2);                              \
            uint32_t bf[2];                                                      \
            bf[0] = Bv[(ks * 8 + (lane & 3)) * GB_ST + n];                       \
            bf[1] = Bv[(ks * 8 + 4 + (lane & 3)) * GB_ST + n];                   \
            mma8(acc[0][ni], af[0], bf);                                         \
            mma8(acc[1][ni], af[1], bf);                                         \
        }                                                                        \
    } } while (0)

    const int NC = K / 16;
    G_LOAD(0, 0);  CP_COMMIT();
    G_LOAD(16, 1); CP_COMMIT();
    G_LOAD(32, 2); CP_COMMIT();
    int st = 0;
    for (int c = 0; c < NC; c++) {
        CP_WAIT(2);
        __syncthreads();
        G_COMP(st);
        int s3 = st + 3; if (s3 >= 4) s3 -= 4;
        if (c + 3 < NC) G_LOAD((c + 3) * 16, s3);
        CP_COMMIT();
        st++; if (st >= 4) st = 0;
    }

#pragma unroll
    for (int mi = 0; mi < 2; mi++)
#pragma unroll
        for (int ni = 0; ni < 8; ni++) {
            int row = rowStart + wm * 32 + mi * 16 + (lane >> 2);
            int col = colStart + wn * 64 + ni * 8 + (lane & 3) * 2;
            float b0 = bias[col], b1 = bias[col + 1];
            float v00 = acc[mi][ni][0] + b0, v01 = acc[mi][ni][1] + b1;
            float v10 = acc[mi][ni][2] + b0, v11 = acc[mi][ni][3] + b1;
            if (ROUND) {
                C[(size_t)row * ldc + col]           = __uint_as_float(f2tf(v00));
                C[(size_t)row * ldc + col + 1]       = __uint_as_float(f2tf(v01));
                C[(size_t)(row + 8) * ldc + col]     = __uint_as_float(f2tf(v10));
                C[(size_t)(row + 8) * ldc + col + 1] = __uint_as_float(f2tf(v11));
            } else {
                C[(size_t)row * ldc + col]           = v00;
                C[(size_t)row * ldc + col + 1]       = v01;
                C[(size_t)(row + 8) * ldc + col]     = v10;
                C[(size_t)(row + 8) * ldc + col + 1] = v11;
            }
        }
}

// ---------------------------------------------------------------------------
// QK^T: per z, 128x128 tile, K=64 single-shot (Q,K pre-rounded in g_qkv).
// smem: Qs[128][68] + Ks[128][68] = 69632 B. Stride 68: 68r%32=4r -> clean.
// ---------------------------------------------------------------------------
#define QK_ST 68
#define QK_SZ (128 * QK_ST)
#define QK_SMEM (2 * QK_SZ * 4)

__global__ __launch_bounds__(256, 2) void qk_tc(
    const float* __restrict__ qkv, const float* __restrict__ mask,
    float* __restrict__ Wout)
{
    extern __shared__ __align__(16) uint32_t sm[];
    uint32_t* Qs = sm;
    uint32_t* Ks = sm + QK_SZ;
    const uint32_t smb = (uint32_t)__cvta_generic_to_shared(sm);

    const int tid = threadIdx.x, lane = tid & 31, warp = tid >> 5;
    const int wm = warp & 3, wn = warp >> 2;
    const int rowStart = blockIdx.y * 128, colStart = blockIdx.x * 128;
    const int z = blockIdx.z, b = z >> 4, h = z & 15;

    const float* Qb = qkv + (size_t)b * SS * 3 * DD + h * HD;
    const float* Kb = Qb + DD;

#pragma unroll
    for (int i = 0; i < 8; i++) {
        int v = tid + i * 256;
        int r = v >> 4, c4 = (v & 15) << 2;
        cp16(smb + (r * QK_ST + c4) * 4,
             &Qb[(size_t)(rowStart + r) * (3 * DD) + c4]);
        cp16(smb + (QK_SZ + r * QK_ST + c4) * 4,
             &Kb[(size_t)(colStart + r) * (3 * DD) + c4]);
    }
    CP_COMMIT();

    float acc[2][8][4];
#pragma unroll
    for (int mi = 0; mi < 2; mi++)
#pragma unroll
        for (int ni = 0; ni < 8; ni++)
#pragma unroll
            for (int r = 0; r < 4; r++) acc[mi][ni][r] = 0.f;

    CP_WAIT(0);
    __syncthreads();

#pragma unroll
    for (int ks = 0; ks < 8; ks++) {
        uint32_t af[2][4];
#pragma unroll
        for (int mi = 0; mi < 2; mi++) {
            int r = wm * 32 + mi * 16 + (lane >> 2);
            int cc = ks * 8 + (lane & 3);
            af[mi][0] = Qs[r * QK_ST + cc];
            af[mi][1] = Qs[(r + 8) * QK_ST + cc];
            af[mi][2] = Qs[r * QK_ST + cc + 4];
            af[mi][3] = Qs[(r + 8) * QK_ST + cc + 4];
        }
#pragma unroll
        for (int ni = 0; ni < 8; ni++) {
            int n = wn * 64 + ni * 8 + (lane >> 2);
            uint32_t bf[2];
            bf[0] = Ks[n * QK_ST + ks * 8 + (lane & 3)];
            bf[1] = Ks[n * QK_ST + ks * 8 + 4 + (lane & 3)];
            mma8(acc[0][ni], af[0], bf);
            mma8(acc[1][ni], af[1], bf);
        }
    }

    const float* mrow = mask + (size_t)b * SS;
#pragma unroll
    for (int mi = 0; mi < 2; mi++)
#pragma unroll
        for (int ni = 0; ni < 8; ni++) {
            int row0 = rowStart + wm * 32 + mi * 16 + (lane >> 2);
            int col = colStart + wn * 64 + ni * 8 + (lane & 3) * 2;
            float m0 = mrow[col], m1 = mrow[col + 1];
#pragma unroll
            for (int half = 0; half < 2; half++) {
                int row = row0 + half * 8;
                float v0 = (row >= col)     ? acc[mi][ni][half * 2 + 0] * 0.125f : -NEG_V;
                float v1 = (row >= col + 1) ? acc[mi][ni][half * 2 + 1] * 0.125f : -NEG_V;
                float* crow = &Wout[((size_t)z * SS + row) * SS + col];
                crow[0] = v0 + m0;
                crow[1] = v1 + m1;
            }
        }
}

// ---------------------------------------------------------------------------
// Row softmax in place: one WARP per row (8 rows per 256-thr block).
// 1024 floats = 8 float4 per lane; all-register, shuffle-only reductions.
// ---------------------------------------------------------------------------
__global__ __launch_bounds__(256) void softmax_rows(float* __restrict__ W)
{
    const int lane = threadIdx.x & 31;
    const int row = blockIdx.x * 8 + (threadIdx.x >> 5);
    float* r = W + (size_t)row * SS;

    float4 v[8];
    float mx = -INFINITY;
#pragma unroll
    for (int c = 0; c < 8; c++) {
        v[c] = *reinterpret_cast<const float4*>(&r[lane * 4 + c * 128]);
        mx = fmaxf(mx, fmaxf(fmaxf(v[c].x, v[c].y), fmaxf(v[c].z, v[c].w)));
    }
#pragma unroll
    for (int o = 16; o > 0; o >>= 1) mx = fmaxf(mx, __shfl_xor_sync(0xffffffffu, mx, o));

    float s = 0.f;
#pragma unroll
    for (int c = 0; c < 8; c++) {
        v[c].x = __expf(v[c].x - mx);
        v[c].y = __expf(v[c].y - mx);
        v[c].z = __expf(v[c].z - mx);
        v[c].w = __expf(v[c].w - mx);
        s += (v[c].x + v[c].y) + (v[c].z + v[c].w);
    }
#pragma unroll
    for (int o = 16; o > 0; o >>= 1) s += __shfl_xor_sync(0xffffffffu, s, o);
    const float inv = 1.0f / s;

#pragma unroll
    for (int c = 0; c < 8; c++) {
        float4 p;
        p.x = v[c].x * inv; p.y = v[c].y * inv;
        p.z = v[c].z * inv; p.w = v[c].w * inv;
        *reinterpret_cast<float4*>(&r[lane * 4 + c * 128]) = p;
    }
}

// ---------------------------------------------------------------------------
// AV: per z, C[1024,64] = W@V. BM=128 BN=64 BK=32, 8 warps (warp 16x64),
// 3-stage cp.async ring. A (probs) converted in-loop; V pre-rounded.
// smem: As[3][128][36] + Bs[3][32][72] = 82944 B.
// ---------------------------------------------------------------------------
#define VA_ST 36
#define VB_ST 72
#define VA_SZ (128 * VA_ST)   // 4608
#define VB_SZ (32 * VB_ST)    // 2304
#define V_SMEM ((3 * (VA_SZ + VB_SZ)) * 4)

__global__ __launch_bounds__(256, 2) void av_tc(
    const float* __restrict__ W, const float* __restrict__ qkv,
    float* __restrict__ Am)
{
    extern __shared__ __align__(16) uint32_t sm[];
    uint32_t* As = sm;
    uint32_t* Bs = sm + 3 * VA_SZ;
    const uint32_t smb = (uint32_t)__cvta_generic_to_shared(sm);

    const int tid = threadIdx.x, lane = tid & 31, warp = tid >> 5;
    const int rowStart = blockIdx.x * 128;
    const int z = blockIdx.y, b = z >> 4, h = z & 15;

    const float* Wb = W + (size_t)z * SS * SS;
    const float* Vb = qkv + (size_t)b * SS * 3 * DD + 2 * DD + h * HD;

    float acc[8][4];
#pragma unroll
    for (int ni = 0; ni < 8; ni++)
#pragma unroll
        for (int r = 0; r < 4; r++) acc[ni][r] = 0.f;

#define V_LOAD(KB0, s) do {                                                      \
    _Pragma("unroll")                                                            \
    for (int i = 0; i < 4; i++) {                                                \
        int v = tid + i * 256;                                                   \
        int r = v >> 3, c4 = (v & 7) << 2;                                       \
        cp16(smb + ((s) * VA_SZ + r * VA_ST + c4) * 4,                           \
             &Wb[(size_t)(rowStart + r) * SS + (KB0) + c4]);                     \
    }                                                                            \
    _Pragma("unroll")                                                            \
    for (int i = 0; i < 2; i++) {                                                \
        int v = tid * 2 + i;                                                     \
        int r = v >> 4, c4 = (v & 15) << 2;                                      \
        cp16(smb + (3 * VA_SZ + (s) * VB_SZ + r * VB_ST + c4) * 4,               \
             &Vb[(size_t)((KB0) + r) * (3 * DD) + c4]);                          \
    } } while (0)

#define V_COMP(s) do {                                                           \
    const uint32_t* Av = As + (s) * VA_SZ;                                       \
    const uint32_t* Bv = Bs + (s) * VB_SZ;                                       \
    _Pragma("unroll")                                                            \
    for (int ks = 0; ks < 4; ks++) {                                             \
        int r = warp * 16 + (lane >> 2);                                         \
        int cc = ks * 8 + (lane & 3);                                            \
        uint32_t af[4];                                                          \
        af[0] = f2tf(__uint_as_float(Av[r * VA_ST + cc]));                       \
        af[1] = f2tf(__uint_as_float(Av[(r + 8) * VA_ST + cc]));                 \
        af[2] = f2tf(__uint_as_float(Av[r * VA_ST + cc + 4]));                   \
        af[3] = f2tf(__uint_as_float(Av[(r + 8) * VA_ST + cc + 4]));             \
        _Pragma("unroll")                                                        \
        for (int ni = 0; ni < 8; ni++) {                                         \
            int n = ni * 8 + (lane >> 2);                                        \
            uint32_t bf[2];                                                      \
            bf[0] = Bv[(ks * 8 + (lane & 3)) * VB_ST + n];                       \
            bf[1] = Bv[(ks * 8 + 4 + (lane & 3)) * VB_ST + n];                   \
            mma8(acc[ni], af, bf);                                               \
        }                                                                        \
    } } while (0)

    const int NC = SS / 32;   // 32 chunks
    V_LOAD(0, 0); CP_COMMIT();
    V_LOAD(32, 1); CP_COMMIT();
    int st = 0;
    for (int c = 0; c < NC; c++) {
        CP_WAIT(1);
        __syncthreads();
        V_COMP(st);
        int s2 = st + 2; if (s2 >= 3) s2 -= 3;
        if (c + 2 < NC) V_LOAD((c + 2) * 32, s2);
        CP_COMMIT();
        st++; if (st >= 3) st = 0;
    }

#pragma unroll
    for (int ni = 0; ni < 8; ni++) {
        int row = rowStart + warp * 16 + (lane >> 2);
        int col = h * HD + ni * 8 + (lane & 3) * 2;
        float* o0 = &Am[((size_t)b * SS + row) * DD + col];
        float* o1 = &Am[((size_t)b * SS + row + 8) * DD + col];
        o0[0] = __uint_as_float(f2tf(acc[ni][0]));
        o0[1] = __uint_as_float(f2tf(acc[ni][1]));
        o1[0] = __uint_as_float(f2tf(acc[ni][2]));
        o1[1] = __uint_as_float(f2tf(acc[ni][3]));
    }
}

// ---------------------------------------------------------------------------
extern "C" void kernel_launch(void* const* d_in, const int* in_sizes, int n_in,
                              void* d_out, int out_size)
{
    const float* x      = (const float*)d_in[0];   // [4,1024,1024]
    const float* mask   = (const float*)d_in[1];   // [4,1,1,1024]
    const float* w_attn = (const float*)d_in[2];   // [1024,3072]
    const float* b_attn = (const float*)d_in[3];   // [1,3072]
    const float* w_proj = (const float*)d_in[4];   // [1024,1024]
    const float* b_proj = (const float*)d_in[5];   // [1,1024]

    float* out = (float*)d_out;
    float* a_out = out;                                  // [4,1024,1024]
    float* w_out = out + (size_t)BB * SS * DD;           // [4,16,1024,1024]

    float *qkv, *am, *xtf, *watf, *wptf;
    cudaGetSymbolAddress((void**)&qkv, g_qkv);
    cudaGetSymbolAddress((void**)&am, g_am);
    cudaGetSymbolAddress((void**)&xtf, g_xtf);
    cudaGetSymbolAddress((void**)&watf, g_watf);
    cudaGetSymbolAddress((void**)&wptf, g_wptf);

    cudaFuncSetAttribute(gemm_tc<true>,
                         cudaFuncAttributeMaxDynamicSharedMemorySize, G_SMEM);
    cudaFuncSetAttribute(gemm_tc<false>,
                         cudaFuncAttributeMaxDynamicSharedMemorySize, G_SMEM);
    cudaFuncSetAttribute(qk_tc,
                         cudaFuncAttributeMaxDynamicSharedMemorySize, QK_SMEM);
    cudaFuncSetAttribute(av_tc,
                         cudaFuncAttributeMaxDynamicSharedMemorySize, V_SMEM);

    // 0) pre-convert inputs to tf32 bit patterns
    cvt_tf32<<<(BB * SS * DD) / 1024, 256>>>(x, xtf);
    cvt_tf32<<<(DD * 3 * DD) / 1024, 256>>>(w_attn, watf);
    cvt_tf32<<<(DD * DD) / 1024, 256>>>(w_proj, wptf);

    // 1) qkv = x @ w_attn + b_attn (rounded to tf32 on write)
    {
        dim3 grid(3 * DD / 128, BB * SS / 128);
        gemm_tc<true><<<grid, 256, G_SMEM>>>(xtf, watf, b_attn, qkv,
                                             DD, DD, 3 * DD, 3 * DD);
    }
    // 2) scores = scale * Q@K^T + causal/mask -> w_out
    {
        dim3 grid(SS / 128, SS / 128, BB * HH);
        qk_tc<<<grid, 256, QK_SMEM>>>(qkv, mask, w_out);
    }
    // 3) softmax rows in place (warp per row)
    softmax_rows<<<BB * HH * SS / 8, 256>>>(w_out);
    // 4) a_heads = W @ V -> merged g_am (rounded)
    {
        dim3 grid(SS / 128, BB * HH);
        av_tc<<<grid, 256, V_SMEM>>>(w_out, qkv, am);
    }
    // 5) a = am @ w_proj + b_proj -> a_out (exact)
    {
        dim3 grid(DD / 128, BB * SS / 128);
        gemm_tc<false><<<grid, 256, G_SMEM>>>(am, wptf, b_proj, a_out,
                                              DD, DD, DD, DD);
    }
}

// round 10
// speedup vs baseline: 1.5788x; 1.0528x over previous
#include <cuda_runtime.h>
#include <math.h>
#include <stdint.h>

// Problem constants
#define BB 4
#define SS 1024
#define DD 1024
#define HH 16
#define HD 64
#define NEG_V 10000.0f

// Scratch (static device arrays; no allocation allowed)
__device__ float g_qkv[BB * SS * 3 * DD];   // [4096,3072] tf32-rounded
__device__ float g_am[BB * SS * DD];        // [4096,1024] tf32-rounded
__device__ float g_xtf[BB * SS * DD];       // x converted to tf32 bits
__device__ float g_watf[DD * 3 * DD];       // w_attn converted
__device__ float g_wptf[DD * DD];           // w_proj converted

// ---------------------------------------------------------------------------
// helpers
// ---------------------------------------------------------------------------
__device__ __forceinline__ uint32_t f2tf(float f) {
    uint32_t u;
    asm("cvt.rna.tf32.f32 %0, %1;" : "=r"(u) : "f"(f));
    return u;
}

__device__ __forceinline__ void mma8(float* c, const uint32_t* a, const uint32_t* b) {
    asm volatile(
        "mma.sync.aligned.m16n8k8.row.col.f32.tf32.tf32.f32 "
        "{%0,%1,%2,%3}, {%4,%5,%6,%7}, {%8,%9}, {%0,%1,%2,%3};\n"
        : "+f"(c[0]), "+f"(c[1]), "+f"(c[2]), "+f"(c[3])
        : "r"(a[0]), "r"(a[1]), "r"(a[2]), "r"(a[3]), "r"(b[0]), "r"(b[1]));
}

__device__ __forceinline__ void cp16(uint32_t dst, const void* src) {
    asm volatile("cp.async.cg.shared.global [%0], [%1], 16;\n" :: "r"(dst), "l"(src));
}
#define CP_COMMIT() asm volatile("cp.async.commit_group;\n" ::: "memory")
#define CP_WAIT(N)  asm volatile("cp.async.wait_group %0;\n" :: "n"(N) : "memory")

// m16n8k8 fragment maps (row.col):
//  A(16x8):  a0=A[g][t] a1=A[g+8][t] a2=A[g][t+4] a3=A[g+8][t+4]  (g=lane>>2,t=lane&3)
//  B(8x8):   b0=B[t][g] b1=B[t+4][g]
//  C(16x8):  c0=C[g][2t] c1=C[g][2t+1] c2=C[g+8][2t] c3=C[g+8][2t+1]

// ---------------------------------------------------------------------------
// Elementwise tf32 pre-convert (n multiple of 1024)
// ---------------------------------------------------------------------------
__global__ __launch_bounds__(256) void cvt_tf32(
    const float* __restrict__ src, float* __restrict__ dst)
{
    int i = (blockIdx.x * 256 + threadIdx.x) * 4;
    float4 v = *reinterpret_cast<const float4*>(src + i);
    uint4 o;
    o.x = f2tf(v.x); o.y = f2tf(v.y); o.z = f2tf(v.z); o.w = f2tf(v.w);
    *reinterpret_cast<uint4*>(dst + i) = o;
}

// ---------------------------------------------------------------------------
// Generic tf32 GEMM on pre-converted inputs: C[M,N] = A@B + bias
// BM=128 BN=128 BK=16, 256 thr (8 warps, warp 32x64), 4-stage cp.async ring.
// ---------------------------------------------------------------------------
#define GA_ST 20
#define GB_ST 136
#define GA_SZ (128 * GA_ST)   // 2560
#define GB_SZ (16 * GB_ST)    // 2176
#define G_SMEM ((4 * (GA_SZ + GB_SZ)) * 4)

template<bool ROUND>
__global__ __launch_bounds__(256, 2) void gemm_tc(
    const float* __restrict__ A, const float* __restrict__ B,
    const float* __restrict__ bias, float* __restrict__ C,
    int K, int lda, int ldb, int ldc)
{
    extern __shared__ __align__(16) uint32_t sm[];
    uint32_t* As = sm;
    uint32_t* Bs = sm + 4 * GA_SZ;
    const uint32_t smb = (uint32_t)__cvta_generic_to_shared(sm);

    const int tid = threadIdx.x, lane = tid & 31, warp = tid >> 5;
    const int wm = warp & 3, wn = warp >> 2;
    const int rowStart = blockIdx.y * 128, colStart = blockIdx.x * 128;

    float acc[2][8][4];
#pragma unroll
    for (int mi = 0; mi < 2; mi++)
#pragma unroll
        for (int ni = 0; ni < 8; ni++)
#pragma unroll
            for (int r = 0; r < 4; r++) acc[mi][ni][r] = 0.f;

#define G_LOAD(KB0, s) do {                                                      \
    _Pragma("unroll")                                                            \
    for (int i = 0; i < 2; i++) {                                                \
        int v = tid * 2 + i;                                                     \
        int r = v >> 2, c4 = (v & 3) << 2;                                       \
        cp16(smb + ((s) * GA_SZ + r * GA_ST + c4) * 4,                           \
             &A[(size_t)(rowStart + r) * lda + (KB0) + c4]);                     \
    }                                                                            \
    _Pragma("unroll")                                                            \
    for (int i = 0; i < 2; i++) {                                                \
        int v = tid * 2 + i;                                                     \
        int r = v >> 5, c4 = (v & 31) << 2;                                      \
        cp16(smb + (4 * GA_SZ + (s) * GB_SZ + r * GB_ST + c4) * 4,               \
             &B[(size_t)((KB0) + r) * ldb + colStart + c4]);                     \
    } } while (0)

#define G_COMP(s) do {                                                           \
    const uint32_t* Av = As + (s) * GA_SZ;                                       \
    const uint32_t* Bv = Bs + (s) * GB_SZ;                                       \
    _Pragma("unroll")                                                            \
    for (int ks = 0; ks < 2; ks++) {                                             \
        uint32_t af[2][4];                                                       \
        _Pragma("unroll")                                                        \
        for (int mi = 0; mi < 2; mi++) {                                         \
            int r = wm * 32 + mi * 16 + (lane >> 2);                             \
            int cc = ks * 8 + (lane & 3);                                        \
            af[mi][0] = Av[r * GA_ST + cc];                                      \
            af[mi][1] = Av[(r + 8) * GA_ST + cc];                                \
            af[mi][2] = Av[r * GA_ST + cc + 4];                                  \
            af[mi][3] = Av[(r + 8) * GA_ST + cc + 4];                            \
        }                                                                        \
        _Pragma("unroll")                                                        \
        for (int ni = 0; ni < 8; ni++) {                                         \
            int n = wn * 64 + ni * 8 + (lane >> 2);                              \
            uint32_t bf[2];                                                      \
            bf[0] = Bv[(ks * 8 + (lane & 3)) * GB_ST + n];                       \
            bf[1] = Bv[(ks * 8 + 4 + (lane & 3)) * GB_ST + n];                   \
            mma8(acc[0][ni], af[0], bf);                                         \
            mma8(acc[1][ni], af[1], bf);                                         \
        }                                                                        \
    } } while (0)

    const int NC = K / 16;
    G_LOAD(0, 0);  CP_COMMIT();
    G_LOAD(16, 1); CP_COMMIT();
    G_LOAD(32, 2); CP_COMMIT();
    int st = 0;
    for (int c = 0; c < NC; c++) {
        CP_WAIT(2);
        __syncthreads();
        G_COMP(st);
        int s3 = st + 3; if (s3 >= 4) s3 -= 4;
        if (c + 3 < NC) G_LOAD((c + 3) * 16, s3);
        CP_COMMIT();
        st++; if (st >= 4) st = 0;
    }

#pragma unroll
    for (int mi = 0; mi < 2; mi++)
#pragma unroll
        for (int ni = 0; ni < 8; ni++) {
            int row = rowStart + wm * 32 + mi * 16 + (lane >> 2);
            int col = colStart + wn * 64 + ni * 8 + (lane & 3) * 2;
            float b0 = bias[col], b1 = bias[col + 1];
            float v00 = acc[mi][ni][0] + b0, v01 = acc[mi][ni][1] + b1;
            float v10 = acc[mi][ni][2] + b0, v11 = acc[mi][ni][3] + b1;
            if (ROUND) {
                C[(size_t)row * ldc + col]           = __uint_as_float(f2tf(v00));
                C[(size_t)row * ldc + col + 1]       = __uint_as_float(f2tf(v01));
                C[(size_t)(row + 8) * ldc + col]     = __uint_as_float(f2tf(v10));
                C[(size_t)(row + 8) * ldc + col + 1] = __uint_as_float(f2tf(v11));
            } else {
                C[(size_t)row * ldc + col]           = v00;
                C[(size_t)row * ldc + col + 1]       = v01;
                C[(size_t)(row + 8) * ldc + col]     = v10;
                C[(size_t)(row + 8) * ldc + col + 1] = v11;
            }
        }
}

// ---------------------------------------------------------------------------
// Fused QK^T + softmax. Per CTA: 16 query rows x all 1024 cols of head z.
// Scores in registers: acc[8 chunks][2][4]. Q fragments resident in regs.
// K chunks (128 x 64) stream via 3-stage cp.async ring.
// Epilogue: scale/causal/mask -> warp (max,sum) -> 8-warp combine -> write
// probabilities once. smem: K 3*128*68 + Q 16*68 words = 108800 B.
// ---------------------------------------------------------------------------
#define FQ_ST 68
#define FK_SZ (128 * FQ_ST)      // 8704 words per K stage
#define FQ_OFF (3 * FK_SZ)       // 26112 words
#define F_SMEM ((FQ_OFF + 16 * FQ_ST) * 4)

__global__ __launch_bounds__(256, 2) void qksm_tc(
    const float* __restrict__ qkv, const float* __restrict__ mask,
    float* __restrict__ Wout)
{
    extern __shared__ __align__(16) uint32_t sm[];
    __shared__ float2 sstat[8][16];
    __shared__ float2 fstat[16];
    const uint32_t smb = (uint32_t)__cvta_generic_to_shared(sm);

    const int tid = threadIdx.x, lane = tid & 31, warp = tid >> 5;
    const int g = lane >> 2, t = lane & 3;
    const int r0 = blockIdx.x * 16;
    const int z = blockIdx.y, b = z >> 4, h = z & 15;

    const float* Qb = qkv + (size_t)b * SS * 3 * DD + h * HD;
    const float* Kb = Qb + DD;

#define FK_LOAD(CH, s) do {                                                      \
    _Pragma("unroll")                                                            \
    for (int i = 0; i < 8; i++) {                                                \
        int v = tid + i * 256;                                                   \
        int r = v >> 4, c4 = (v & 15) << 2;                                      \
        cp16(smb + ((s) * FK_SZ + r * FQ_ST + c4) * 4,                           \
             &Kb[(size_t)((CH) * 128 + r) * (3 * DD) + c4]);                     \
    } } while (0)

    // prologue: Q + K0 in group0, K1 in group1
    {
        int r = tid >> 4, c4 = (tid & 15) << 2;
        cp16(smb + (FQ_OFF + r * FQ_ST + c4) * 4,
             &Qb[(size_t)(r0 + r) * (3 * DD) + c4]);
    }
    FK_LOAD(0, 0); CP_COMMIT();
    FK_LOAD(1, 1); CP_COMMIT();

    CP_WAIT(1);
    __syncthreads();   // Q + K0 ready

    // Q fragments resident (32 regs)
    uint32_t qf[8][4];
    {
        const uint32_t* Qs = sm + FQ_OFF;
#pragma unroll
        for (int ks = 0; ks < 8; ks++) {
            qf[ks][0] = Qs[g * FQ_ST + ks * 8 + t];
            qf[ks][1] = Qs[(g + 8) * FQ_ST + ks * 8 + t];
            qf[ks][2] = Qs[g * FQ_ST + ks * 8 + 4 + t];
            qf[ks][3] = Qs[(g + 8) * FQ_ST + ks * 8 + 4 + t];
        }
    }

    float acc[8][2][4];
#pragma unroll
    for (int c = 0; c < 8; c++)
#pragma unroll
        for (int ni = 0; ni < 2; ni++)
#pragma unroll
            for (int r = 0; r < 4; r++) acc[c][ni][r] = 0.f;

#pragma unroll
    for (int c = 0; c < 8; c++) {
        CP_WAIT(1);
        __syncthreads();
        const uint32_t* Kv = sm + (c % 3) * FK_SZ;
#pragma unroll
        for (int ks = 0; ks < 8; ks++) {
#pragma unroll
            for (int ni = 0; ni < 2; ni++) {
                int nl = warp * 16 + ni * 8 + g;
                uint32_t bf[2];
                bf[0] = Kv[nl * FQ_ST + ks * 8 + t];
                bf[1] = Kv[nl * FQ_ST + ks * 8 + 4 + t];
                mma8(acc[c][ni], qf[ks], bf);
            }
        }
        if (c + 2 < 8) FK_LOAD(c + 2, (c + 2) % 3);
        CP_COMMIT();
    }

    // ---- epilogue: scale + causal + mask, row max ----
    const float* mrow = mask + (size_t)b * SS;
    const int row0 = r0 + g, row1 = r0 + g + 8;
    float m0 = -1e30f, m1 = -1e30f;
#pragma unroll
    for (int c = 0; c < 8; c++)
#pragma unroll
        for (int ni = 0; ni < 2; ni++) {
            int col0 = c * 128 + warp * 16 + ni * 8 + 2 * t;
            float2 mv = *reinterpret_cast<const float2*>(&mrow[col0]);
            float v0 = ((row0 >= col0)     ? acc[c][ni][0] * 0.125f : -NEG_V) + mv.x;
            float v1 = ((row0 >= col0 + 1) ? acc[c][ni][1] * 0.125f : -NEG_V) + mv.y;
            float v2 = ((row1 >= col0)     ? acc[c][ni][2] * 0.125f : -NEG_V) + mv.x;
            float v3 = ((row1 >= col0 + 1) ? acc[c][ni][3] * 0.125f : -NEG_V) + mv.y;
            acc[c][ni][0] = v0; acc[c][ni][1] = v1;
            acc[c][ni][2] = v2; acc[c][ni][3] = v3;
            m0 = fmaxf(m0, fmaxf(v0, v1));
            m1 = fmaxf(m1, fmaxf(v2, v3));
        }
    m0 = fmaxf(m0, __shfl_xor_sync(0xffffffffu, m0, 1));
    m0 = fmaxf(m0, __shfl_xor_sync(0xffffffffu, m0, 2));
    m1 = fmaxf(m1, __shfl_xor_sync(0xffffffffu, m1, 1));
    m1 = fmaxf(m1, __shfl_xor_sync(0xffffffffu, m1, 2));

    // exp with warp-local max; cache exponentials in acc
    float s0 = 0.f, s1 = 0.f;
#pragma unroll
    for (int c = 0; c < 8; c++)
#pragma unroll
        for (int ni = 0; ni < 2; ni++) {
            float e0 = __expf(acc[c][ni][0] - m0);
            float e1 = __expf(acc[c][ni][1] - m0);
            float e2 = __expf(acc[c][ni][2] - m1);
            float e3 = __expf(acc[c][ni][3] - m1);
            acc[c][ni][0] = e0; acc[c][ni][1] = e1;
            acc[c][ni][2] = e2; acc[c][ni][3] = e3;
            s0 += e0 + e1; s1 += e2 + e3;
        }
    s0 += __shfl_xor_sync(0xffffffffu, s0, 1);
    s0 += __shfl_xor_sync(0xffffffffu, s0, 2);
    s1 += __shfl_xor_sync(0xffffffffu, s1, 1);
    s1 += __shfl_xor_sync(0xffffffffu, s1, 2);

    if (t == 0) {
        sstat[warp][g]     = make_float2(m0, s0);
        sstat[warp][g + 8] = make_float2(m1, s1);
    }
    __syncthreads();
    if (tid < 16) {
        float M = -1e30f;
#pragma unroll
        for (int w = 0; w < 8; w++) M = fmaxf(M, sstat[w][tid].x);
        float S = 0.f;
#pragma unroll
        for (int w = 0; w < 8; w++) S += sstat[w][tid].y * __expf(sstat[w][tid].x - M);
        fstat[tid] = make_float2(M, 1.0f / S);
    }
    __syncthreads();

    const float2 fs0 = fstat[g], fs1 = fstat[g + 8];
    const float f0 = __expf(m0 - fs0.x) * fs0.y;
    const float f1 = __expf(m1 - fs1.x) * fs1.y;

    float* wr0 = &Wout[((size_t)z * SS + row0) * SS];
    float* wr1 = &Wout[((size_t)z * SS + row1) * SS];
#pragma unroll
    for (int c = 0; c < 8; c++)
#pragma unroll
        for (int ni = 0; ni < 2; ni++) {
            int col0 = c * 128 + warp * 16 + ni * 8 + 2 * t;
            float2 p01, p23;
            p01.x = acc[c][ni][0] * f0; p01.y = acc[c][ni][1] * f0;
            p23.x = acc[c][ni][2] * f1; p23.y = acc[c][ni][3] * f1;
            *reinterpret_cast<float2*>(&wr0[col0]) = p01;
            *reinterpret_cast<float2*>(&wr1[col0]) = p23;
        }
}

// ---------------------------------------------------------------------------
// AV: per z, C[1024,64] = W@V. BM=128 BN=64 BK=32, 8 warps (warp 16x64),
// 3-stage cp.async ring. A (probs) converted in-loop; V pre-rounded.
// ---------------------------------------------------------------------------
#define VA_ST 36
#define VB_ST 72
#define VA_SZ (128 * VA_ST)   // 4608
#define VB_SZ (32 * VB_ST)    // 2304
#define V_SMEM ((3 * (VA_SZ + VB_SZ)) * 4)

__global__ __launch_bounds__(256, 2) void av_tc(
    const float* __restrict__ W, const float* __restrict__ qkv,
    float* __restrict__ Am)
{
    extern __shared__ __align__(16) uint32_t sm[];
    uint32_t* As = sm;
    uint32_t* Bs = sm + 3 * VA_SZ;
    const uint32_t smb = (uint32_t)__cvta_generic_to_shared(sm);

    const int tid = threadIdx.x, lane = tid & 31, warp = tid >> 5;
    const int rowStart = blockIdx.x * 128;
    const int z = blockIdx.y, b = z >> 4, h = z & 15;

    const float* Wb = W + (size_t)z * SS * SS;
    const float* Vb = qkv + (size_t)b * SS * 3 * DD + 2 * DD + h * HD;

    float acc[8][4];
#pragma unroll
    for (int ni = 0; ni < 8; ni++)
#pragma unroll
        for (int r = 0; r < 4; r++) acc[ni][r] = 0.f;

#define V_LOAD(KB0, s) do {                                                      \
    _Pragma("unroll")                                                            \
    for (int i = 0; i < 4; i++) {                                                \
        int v = tid + i * 256;                                                   \
        int r = v >> 3, c4 = (v & 7) << 2;                                       \
        cp16(smb + ((s) * VA_SZ + r * VA_ST + c4) * 4,                           \
             &Wb[(size_t)(rowStart + r) * SS + (KB0) + c4]);                     \
    }                                                                            \
    _Pragma("unroll")                                                            \
    for (int i = 0; i < 2; i++) {                                                \
        int v = tid * 2 + i;                                                     \
        int r = v >> 4, c4 = (v & 15) << 2;                                      \
        cp16(smb + (3 * VA_SZ + (s) * VB_SZ + r * VB_ST + c4) * 4,               \
             &Vb[(size_t)((KB0) + r) * (3 * DD) + c4]);                          \
    } } while (0)

#define V_COMP(s) do {                                                           \
    const uint32_t* Av = As + (s) * VA_SZ;                                       \
    const uint32_t* Bv = Bs + (s) * VB_SZ;                                       \
    _Pragma("unroll")                                                            \
    for (int ks = 0; ks < 4; ks++) {                                             \
        int r = warp * 16 + (lane >> 2);                                         \
        int cc = ks * 8 + (lane & 3);                                            \
        uint32_t af[4];                                                          \
        af[0] = f2tf(__uint_as_float(Av[r * VA_ST + cc]));                       \
        af[1] = f2tf(__uint_as_float(Av[(r + 8) * VA_ST + cc]));                 \
        af[2] = f2tf(__uint_as_float(Av[r * VA_ST + cc + 4]));                   \
        af[3] = f2tf(__uint_as_float(Av[(r + 8) * VA_ST + cc + 4]));             \
        _Pragma("unroll")                                                        \
        for (int ni = 0; ni < 8; ni++) {                                         \
            int n = ni * 8 + (lane >> 2);                                        \
            uint32_t bf[2];                                                      \
            bf[0] = Bv[(ks * 8 + (lane & 3)) * VB_ST + n];                       \
            bf[1] = Bv[(ks * 8 + 4 + (lane & 3)) * VB_ST + n];                   \
            mma8(acc[ni], af, bf);                                               \
        }                                                                        \
    } } while (0)

    const int NC = SS / 32;   // 32 chunks
    V_LOAD(0, 0); CP_COMMIT();
    V_LOAD(32, 1); CP_COMMIT();
    int st = 0;
    for (int c = 0; c < NC; c++) {
        CP_WAIT(1);
        __syncthreads();
        V_COMP(st);
        int s2 = st + 2; if (s2 >= 3) s2 -= 3;
        if (c + 2 < NC) V_LOAD((c + 2) * 32, s2);
        CP_COMMIT();
        st++; if (st >= 3) st = 0;
    }

#pragma unroll
    for (int ni = 0; ni < 8; ni++) {
        int row = rowStart + warp * 16 + (lane >> 2);
        int col = h * HD + ni * 8 + (lane & 3) * 2;
        float* o0 = &Am[((size_t)b * SS + row) * DD + col];
        float* o1 = &Am[((size_t)b * SS + row + 8) * DD + col];
        o0[0] = __uint_as_float(f2tf(acc[ni][0]));
        o0[1] = __uint_as_float(f2tf(acc[ni][1]));
        o1[0] = __uint_as_float(f2tf(acc[ni][2]));
        o1[1] = __uint_as_float(f2tf(acc[ni][3]));
    }
}

// ---------------------------------------------------------------------------
extern "C" void kernel_launch(void* const* d_in, const int* in_sizes, int n_in,
                              void* d_out, int out_size)
{
    const float* x      = (const float*)d_in[0];   // [4,1024,1024]
    const float* mask   = (const float*)d_in[1];   // [4,1,1,1024]
    const float* w_attn = (const float*)d_in[2];   // [1024,3072]
    const float* b_attn = (const float*)d_in[3];   // [1,3072]
    const float* w_proj = (const float*)d_in[4];   // [1024,1024]
    const float* b_proj = (const float*)d_in[5];   // [1,1024]

    float* out = (float*)d_out;
    float* a_out = out;                                  // [4,1024,1024]
    float* w_out = out + (size_t)BB * SS * DD;           // [4,16,1024,1024]

    float *qkv, *am, *xtf, *watf, *wptf;
    cudaGetSymbolAddress((void**)&qkv, g_qkv);
    cudaGetSymbolAddress((void**)&am, g_am);
    cudaGetSymbolAddress((void**)&xtf, g_xtf);
    cudaGetSymbolAddress((void**)&watf, g_watf);
    cudaGetSymbolAddress((void**)&wptf, g_wptf);

    cudaFuncSetAttribute(gemm_tc<true>,
                         cudaFuncAttributeMaxDynamicSharedMemorySize, G_SMEM);
    cudaFuncSetAttribute(gemm_tc<false>,
                         cudaFuncAttributeMaxDynamicSharedMemorySize, G_SMEM);
    cudaFuncSetAttribute(qksm_tc,
                         cudaFuncAttributeMaxDynamicSharedMemorySize, F_SMEM);
    cudaFuncSetAttribute(av_tc,
                         cudaFuncAttributeMaxDynamicSharedMemorySize, V_SMEM);

    // 0) pre-convert inputs to tf32 bit patterns
    cvt_tf32<<<(BB * SS * DD) / 1024, 256>>>(x, xtf);
    cvt_tf32<<<(DD * 3 * DD) / 1024, 256>>>(w_attn, watf);
    cvt_tf32<<<(DD * DD) / 1024, 256>>>(w_proj, wptf);

    // 1) qkv = x @ w_attn + b_attn (rounded to tf32 on write)
    {
        dim3 grid(3 * DD / 128, BB * SS / 128);
        gemm_tc<true><<<grid, 256, G_SMEM>>>(xtf, watf, b_attn, qkv,
                                             DD, DD, 3 * DD, 3 * DD);
    }
    // 2) fused scores + softmax -> probabilities in w_out
    {
        dim3 grid(SS / 16, BB * HH);
        qksm_tc<<<grid, 256, F_SMEM>>>(qkv, mask, w_out);
    }
    // 3) a_heads = W @ V -> merged g_am (rounded)
    {
        dim3 grid(SS / 128, BB * HH);
        av_tc<<<grid, 256, V_SMEM>>>(w_out, qkv, am);
    }
    // 4) a = am @ w_proj + b_proj -> a_out (exact)
    {
        dim3 grid(DD / 128, BB * SS / 128);
        gemm_tc<false><<<grid, 256, G_SMEM>>>(am, wptf, b_proj, a_out,
                                              DD, DD, DD, DD);
    }
}

// round 13
// speedup vs baseline: 1.7734x; 1.1233x over previous
#include <cuda_runtime.h>
#include <math.h>
#include <stdint.h>

// Problem constants
#define BB 4
#define SS 1024
#define DD 1024
#define HH 16
#define HD 64
#define NEG_V 10000.0f

// Scratch (static device arrays; no allocation allowed)
__device__ float g_qkv[BB * SS * 3 * DD];   // [4096,3072] tf32-rounded
__device__ float g_am[BB * SS * DD];        // [4096,1024] tf32-rounded
__device__ float g_xtf[BB * SS * DD];       // x converted to tf32 bits
__device__ float g_watf[DD * 3 * DD];       // w_attn converted
__device__ float g_wptf[DD * DD];           // w_proj converted

// ---------------------------------------------------------------------------
// helpers
// ---------------------------------------------------------------------------
__device__ __forceinline__ uint32_t f2tf(float f) {
    uint32_t u;
    asm("cvt.rna.tf32.f32 %0, %1;" : "=r"(u) : "f"(f));
    return u;
}

__device__ __forceinline__ void mma8(float* c, const uint32_t* a, const uint32_t* b) {
    asm volatile(
        "mma.sync.aligned.m16n8k8.row.col.f32.tf32.tf32.f32 "
        "{%0,%1,%2,%3}, {%4,%5,%6,%7}, {%8,%9}, {%0,%1,%2,%3};\n"
        : "+f"(c[0]), "+f"(c[1]), "+f"(c[2]), "+f"(c[3])
        : "r"(a[0]), "r"(a[1]), "r"(a[2]), "r"(a[3]), "r"(b[0]), "r"(b[1]));
}

__device__ __forceinline__ void cp16(uint32_t dst, const void* src) {
    asm volatile("cp.async.cg.shared.global [%0], [%1], 16;\n" :: "r"(dst), "l"(src));
}
#define CP_COMMIT() asm volatile("cp.async.commit_group;\n" ::: "memory")
#define CP_WAIT(N)  asm volatile("cp.async.wait_group %0;\n" :: "n"(N) : "memory")

// ---------------------------------------------------------------------------
// Elementwise tf32 pre-convert (n multiple of 1024)
// ---------------------------------------------------------------------------
__global__ __launch_bounds__(256) void cvt_tf32(
    const float* __restrict__ src, float* __restrict__ dst)
{
    int i = (blockIdx.x * 256 + threadIdx.x) * 4;
    float4 v = *reinterpret_cast<const float4*>(src + i);
    uint4 o;
    o.x = f2tf(v.x); o.y = f2tf(v.y); o.z = f2tf(v.z); o.w = f2tf(v.w);
    *reinterpret_cast<uint4*>(dst + i) = o;
}

// ---------------------------------------------------------------------------
// Generic tf32 GEMM on pre-converted inputs: C[M,N] = A@B + bias
// BM=128 BN=128 BK=16, 256 thr (8 warps, warp 32x64), 4-stage cp.async ring.
// ---------------------------------------------------------------------------
#define GA_ST 20
#define GB_ST 136
#define GA_SZ (128 * GA_ST)   // 2560
#define GB_SZ (16 * GB_ST)    // 2176
#define G_SMEM ((4 * (GA_SZ + GB_SZ)) * 4)

template<bool ROUND>
__global__ __launch_bounds__(256, 2) void gemm_tc(
    const float* __restrict__ A, const float* __restrict__ B,
    const float* __restrict__ bias, float* __restrict__ C,
    int K, int lda, int ldb, int ldc)
{
    extern __shared__ __align__(16) uint32_t sm[];
    uint32_t* As = sm;
    uint32_t* Bs = sm + 4 * GA_SZ;
    const uint32_t smb = (uint32_t)__cvta_generic_to_shared(sm);

    const int tid = threadIdx.x, lane = tid & 31, warp = tid >> 5;
    const int wm = warp & 3, wn = warp >> 2;
    const int rowStart = blockIdx.y * 128, colStart = blockIdx.x * 128;

    float acc[2][8][4];
#pragma unroll
    for (int mi = 0; mi < 2; mi++)
#pragma unroll
        for (int ni = 0; ni < 8; ni++)
#pragma unroll
            for (int r = 0; r < 4; r++) acc[mi][ni][r] = 0.f;

#define G_LOAD(KB0, s) do {                                                      \
    _Pragma("unroll")                                                            \
    for (int i = 0; i < 2; i++) {                                                \
        int v = tid * 2 + i;                                                     \
        int r = v >> 2, c4 = (v & 3) << 2;                                       \
        cp16(smb + ((s) * GA_SZ + r * GA_ST + c4) * 4,                           \
             &A[(size_t)(rowStart + r) * lda + (KB0) + c4]);                     \
    }                                                                            \
    _Pragma("unroll")                                                            \
    for (int i = 0; i < 2; i++) {                                                \
        int v = tid * 2 + i;                                                     \
        int r = v >> 5, c4 = (v & 31) << 2;                                      \
        cp16(smb + (4 * GA_SZ + (s) * GB_SZ + r * GB_ST + c4) * 4,               \
             &B[(size_t)((KB0) + r) * ldb + colStart + c4]);                     \
    } } while (0)

#define G_COMP(s) do {                                                           \
    const uint32_t* Av = As + (s) * GA_SZ;                                       \
    const uint32_t* Bv = Bs + (s) * GB_SZ;                                       \
    _Pragma("unroll")                                                            \
    for (int ks = 0; ks < 2; ks++) {                                             \
        uint32_t af[2][4];                                                       \
        _Pragma("unroll")                                                        \
        for (int mi = 0; mi < 2; mi++) {                                         \
            int r = wm * 32 + mi * 16 + (lane >> 2);                             \
            int cc = ks * 8 + (lane & 3);                                        \
            af[mi][0] = Av[r * GA_ST + cc];                                      \
            af[mi][1] = Av[(r + 8) * GA_ST + cc];                                \
            af[mi][2] = Av[r * GA_ST + cc + 4];                                  \
            af[mi][3] = Av[(r + 8) * GA_ST + cc + 4];                            \
        }                                                                        \
        _Pragma("unroll")                                                        \
        for (int ni = 0; ni < 8; ni++) {                                         \
            int n = wn * 64 + ni * 8 + (lane >> 2);                              \
            uint32_t bf[2];                                                      \
            bf[0] = Bv[(ks * 8 + (lane & 3)) * GB_ST + n];                       \
            bf[1] = Bv[(ks * 8 + 4 + (lane & 3)) * GB_ST + n];                   \
            mma8(acc[0][ni], af[0], bf);                                         \
            mma8(acc[1][ni], af[1], bf);                                         \
        }                                                                        \
    } } while (0)

    const int NC = K / 16;
    G_LOAD(0, 0);  CP_COMMIT();
    G_LOAD(16, 1); CP_COMMIT();
    G_LOAD(32, 2); CP_COMMIT();
    int st = 0;
    for (int c = 0; c < NC; c++) {
        CP_WAIT(2);
        __syncthreads();
        G_COMP(st);
        int s3 = st + 3; if (s3 >= 4) s3 -= 4;
        if (c + 3 < NC) G_LOAD((c + 3) * 16, s3);
        CP_COMMIT();
        st++; if (st >= 4) st = 0;
    }

#pragma unroll
    for (int mi = 0; mi < 2; mi++)
#pragma unroll
        for (int ni = 0; ni < 8; ni++) {
            int row = rowStart + wm * 32 + mi * 16 + (lane >> 2);
            int col = colStart + wn * 64 + ni * 8 + (lane & 3) * 2;
            float b0 = bias[col], b1 = bias[col + 1];
            float v00 = acc[mi][ni][0] + b0, v01 = acc[mi][ni][1] + b1;
            float v10 = acc[mi][ni][2] + b0, v11 = acc[mi][ni][3] + b1;
            if (ROUND) {
                C[(size_t)row * ldc + col]           = __uint_as_float(f2tf(v00));
                C[(size_t)row * ldc + col + 1]       = __uint_as_float(f2tf(v01));
                C[(size_t)(row + 8) * ldc + col]     = __uint_as_float(f2tf(v10));
                C[(size_t)(row + 8) * ldc + col + 1] = __uint_as_float(f2tf(v11));
            } else {
                C[(size_t)row * ldc + col]           = v00;
                C[(size_t)row * ldc + col + 1]       = v01;
                C[(size_t)(row + 8) * ldc + col]     = v10;
                C[(size_t)(row + 8) * ldc + col + 1] = v11;
            }
        }
}

// ---------------------------------------------------------------------------
// Fused QK^T + softmax with CAUSAL CHUNK SKIPPING.
// Per CTA: 16 query rows x all 1024 cols of head z. Chunks (128 cols) with
// c*128 > r0+15 are fully masked -> probs are exactly 0 (exp underflow);
// skip their K loads + mma + exp, write zeros. NCz = (r0+15)/128 + 1.
// Probs are written tf32-pre-rounded so AV needs no in-loop cvt.
// ---------------------------------------------------------------------------
#define FQ_ST 68
#define FK_SZ (128 * FQ_ST)
#define FQ_OFF (3 * FK_SZ)
#define F_SMEM ((FQ_OFF + 16 * FQ_ST) * 4)

__global__ __launch_bounds__(256, 2) void qksm_tc(
    const float* __restrict__ qkv, const float* __restrict__ mask,
    float* __restrict__ Wout)
{
    extern __shared__ __align__(16) uint32_t sm[];
    __shared__ float2 sstat[8][16];
    __shared__ float2 fstat[16];
    const uint32_t smb = (uint32_t)__cvta_generic_to_shared(sm);

    const int tid = threadIdx.x, lane = tid & 31, warp = tid >> 5;
    const int g = lane >> 2, t = lane & 3;
    const int r0 = blockIdx.x * 16;
    const int z = blockIdx.y, b = z >> 4, h = z & 15;
    const int NCz = ((r0 + 15) >> 7) + 1;     // live chunks: 1..8

    const float* Qb = qkv + (size_t)b * SS * 3 * DD + h * HD;
    const float* Kb = Qb + DD;

#define FK_LOAD(CH, s) do {                                                      \
    _Pragma("unroll")                                                            \
    for (int i = 0; i < 8; i++) {                                                \
        int v = tid + i * 256;                                                   \
        int r = v >> 4, c4 = (v & 15) << 2;                                      \
        cp16(smb + ((s) * FK_SZ + r * FQ_ST + c4) * 4,                           \
             &Kb[(size_t)((CH) * 128 + r) * (3 * DD) + c4]);                     \
    } } while (0)

    {
        int r = tid >> 4, c4 = (tid & 15) << 2;
        cp16(smb + (FQ_OFF + r * FQ_ST + c4) * 4,
             &Qb[(size_t)(r0 + r) * (3 * DD) + c4]);
    }
    FK_LOAD(0, 0); CP_COMMIT();
    if (NCz > 1) FK_LOAD(1, 1);
    CP_COMMIT();

    CP_WAIT(1);
    __syncthreads();

    uint32_t qf[8][4];
    {
        const uint32_t* Qs = sm + FQ_OFF;
#pragma unroll
        for (int ks = 0; ks < 8; ks++) {
            qf[ks][0] = Qs[g * FQ_ST + ks * 8 + t];
            qf[ks][1] = Qs[(g + 8) * FQ_ST + ks * 8 + t];
            qf[ks][2] = Qs[g * FQ_ST + ks * 8 + 4 + t];
            qf[ks][3] = Qs[(g + 8) * FQ_ST + ks * 8 + 4 + t];
        }
    }

    float acc[8][2][4];
#pragma unroll
    for (int c = 0; c < 8; c++)
#pragma unroll
        for (int ni = 0; ni < 2; ni++)
#pragma unroll
            for (int r = 0; r < 4; r++) acc[c][ni][r] = 0.f;

#pragma unroll
    for (int c = 0; c < 8; c++) {
        if (c >= NCz) break;
        CP_WAIT(1);
        __syncthreads();
        const uint32_t* Kv = sm + (c % 3) * FK_SZ;
#pragma unroll
        for (int ks = 0; ks < 8; ks++) {
#pragma unroll
            for (int ni = 0; ni < 2; ni++) {
                int nl = warp * 16 + ni * 8 + g;
                uint32_t bf[2];
                bf[0] = Kv[nl * FQ_ST + ks * 8 + t];
                bf[1] = Kv[nl * FQ_ST + ks * 8 + 4 + t];
                mma8(acc[c][ni], qf[ks], bf);
            }
        }
        if (c + 2 < NCz) FK_LOAD(c + 2, (c + 2) % 3);
        CP_COMMIT();
    }

    // epilogue: scale + causal + mask + row max over LIVE chunks
    const float* mrow = mask + (size_t)b * SS;
    const int row0 = r0 + g, row1 = r0 + g + 8;
    float m0 = -1e30f, m1 = -1e30f;
#pragma unroll
    for (int c = 0; c < 8; c++) {
        if (c >= NCz) break;
#pragma unroll
        for (int ni = 0; ni < 2; ni++) {
            int col0 = c * 128 + warp * 16 + ni * 8 + 2 * t;
            float2 mv = *reinterpret_cast<const float2*>(&mrow[col0]);
            float v0 = ((row0 >= col0)     ? acc[c][ni][0] * 0.125f : -NEG_V) + mv.x;
            float v1 = ((row0 >= col0 + 1) ? acc[c][ni][1] * 0.125f : -NEG_V) + mv.y;
            float v2 = ((row1 >= col0)     ? acc[c][ni][2] * 0.125f : -NEG_V) + mv.x;
            float v3 = ((row1 >= col0 + 1) ? acc[c][ni][3] * 0.125f : -NEG_V) + mv.y;
            acc[c][ni][0] = v0; acc[c][ni][1] = v1;
            acc[c][ni][2] = v2; acc[c][ni][3] = v3;
            m0 = fmaxf(m0, fmaxf(v0, v1));
            m1 = fmaxf(m1, fmaxf(v2, v3));
        }
    }
    m0 = fmaxf(m0, __shfl_xor_sync(0xffffffffu, m0, 1));
    m0 = fmaxf(m0, __shfl_xor_sync(0xffffffffu, m0, 2));
    m1 = fmaxf(m1, __shfl_xor_sync(0xffffffffu, m1, 1));
    m1 = fmaxf(m1, __shfl_xor_sync(0xffffffffu, m1, 2));

    float s0 = 0.f, s1 = 0.f;
#pragma unroll
    for (int c = 0; c < 8; c++) {
        if (c >= NCz) break;
#pragma unroll
        for (int ni = 0; ni < 2; ni++) {
            float e0 = __expf(acc[c][ni][0] - m0);
            float e1 = __expf(acc[c][ni][1] - m0);
            float e2 = __expf(acc[c][ni][2] - m1);
            float e3 = __expf(acc[c][ni][3] - m1);
            acc[c][ni][0] = e0; acc[c][ni][1] = e1;
            acc[c][ni][2] = e2; acc[c][ni][3] = e3;
            s0 += e0 + e1; s1 += e2 + e3;
        }
    }
    s0 += __shfl_xor_sync(0xffffffffu, s0, 1);
    s0 += __shfl_xor_sync(0xffffffffu, s0, 2);
    s1 += __shfl_xor_sync(0xffffffffu, s1, 1);
    s1 += __shfl_xor_sync(0xffffffffu, s1, 2);

    if (t == 0) {
        sstat[warp][g]     = make_float2(m0, s0);
        sstat[warp][g + 8] = make_float2(m1, s1);
    }
    __syncthreads();
    if (tid < 16) {
        float M = -1e30f;
#pragma unroll
        for (int w = 0; w < 8; w++) M = fmaxf(M, sstat[w][tid].x);
        float S = 0.f;
#pragma unroll
        for (int w = 0; w < 8; w++) S += sstat[w][tid].y * __expf(sstat[w][tid].x - M);
        fstat[tid] = make_float2(M, 1.0f / S);
    }
    __syncthreads();

    const float2 fs0 = fstat[g], fs1 = fstat[g + 8];
    const float f0 = __expf(m0 - fs0.x) * fs0.y;
    const float f1 = __expf(m1 - fs1.x) * fs1.y;

    float* wr0 = &Wout[((size_t)z * SS + row0) * SS];
    float* wr1 = &Wout[((size_t)z * SS + row1) * SS];
#pragma unroll
    for (int c = 0; c < 8; c++) {
#pragma unroll
        for (int ni = 0; ni < 2; ni++) {
            int col0 = c * 128 + warp * 16 + ni * 8 + 2 * t;
            float2 p01, p23;
            if (c < NCz) {
                p01.x = __uint_as_float(f2tf(acc[c][ni][0] * f0));
                p01.y = __uint_as_float(f2tf(acc[c][ni][1] * f0));
                p23.x = __uint_as_float(f2tf(acc[c][ni][2] * f1));
                p23.y = __uint_as_float(f2tf(acc[c][ni][3] * f1));
            } else {
                p01.x = 0.f; p01.y = 0.f; p23.x = 0.f; p23.y = 0.f;
            }
            *reinterpret_cast<float2*>(&wr0[col0]) = p01;
            *reinterpret_cast<float2*>(&wr1[col0]) = p23;
        }
    }
}

// ---------------------------------------------------------------------------
// AV with causal chunk skipping: probs beyond row block are exactly 0 ->
// only NC = 4*bx + 4 chunks contribute. Probs are pre-rounded tf32: no cvt.
// BM=128 BN=64 BK=32, 8 warps (warp 16x64), 3-stage cp.async ring.
// ---------------------------------------------------------------------------
#define VA_ST 36
#define VB_ST 72
#define VA_SZ (128 * VA_ST)
#define VB_SZ (32 * VB_ST)
#define V_SMEM ((3 * (VA_SZ + VB_SZ)) * 4)

__global__ __launch_bounds__(256, 2) void av_tc(
    const float* __restrict__ W, const float* __restrict__ qkv,
    float* __restrict__ Am)
{
    extern __shared__ __align__(16) uint32_t sm[];
    uint32_t* As = sm;
    uint32_t* Bs = sm + 3 * VA_SZ;
    const uint32_t smb = (uint32_t)__cvta_generic_to_shared(sm);

    const int tid = threadIdx.x, lane = tid & 31, warp = tid >> 5;
    const int rowStart = blockIdx.x * 128;
    const int z = blockIdx.y, b = z >> 4, h = z & 15;
    const int NC = 4 * blockIdx.x + 4;     // live K chunks (causal)

    const float* Wb = W + (size_t)z * SS * SS;
    const float* Vb = qkv + (size_t)b * SS * 3 * DD + 2 * DD + h * HD;

    float acc[8][4];
#pragma unroll
    for (int ni = 0; ni < 8; ni++)
#pragma unroll
        for (int r = 0; r < 4; r++) acc[ni][r] = 0.f;

#define V_LOAD(KB0, s) do {                                                      \
    _Pragma("unroll")                                                            \
    for (int i = 0; i < 4; i++) {                                                \
        int v = tid + i * 256;                                                   \
        int r = v >> 3, c4 = (v & 7) << 2;                                       \
        cp16(smb + ((s) * VA_SZ + r * VA_ST + c4) * 4,                           \
             &Wb[(size_t)(rowStart + r) * SS + (KB0) + c4]);                     \
    }                                                                            \
    _Pragma("unroll")                                                            \
    for (int i = 0; i < 2; i++) {                                                \
        int v = tid * 2 + i;                                                     \
        int r = v >> 4, c4 = (v & 15) << 2;                                      \
        cp16(smb + (3 * VA_SZ + (s) * VB_SZ + r * VB_ST + c4) * 4,               \
             &Vb[(size_t)((KB0) + r) * (3 * DD) + c4]);                          \
    } } while (0)

#define V_COMP(s) do {                                                           \
    const uint32_t* Av = As + (s) * VA_SZ;                                       \
    const uint32_t* Bv = Bs + (s) * VB_SZ;                                       \
    _Pragma("unroll")                                                            \
    for (int ks = 0; ks < 4; ks++) {                                             \
        int r = warp * 16 + (lane >> 2);                                         \
        int cc = ks * 8 + (lane & 3);                                            \
        uint32_t af[4];                                                          \
        af[0] = Av[r * VA_ST + cc];                                              \
        af[1] = Av[(r + 8) * VA_ST + cc];                                        \
        af[2] = Av[r * VA_ST + cc + 4];                                          \
        af[3] = Av[(r + 8) * VA_ST + cc + 4];                                    \
        _Pragma("unroll")                                                        \
        for (int ni = 0; ni < 8; ni++) {                                         \
            int n = ni * 8 + (lane >> 2);                                        \
            uint32_t bf[2];                                                      \
            bf[0] = Bv[(ks * 8 + (lane & 3)) * VB_ST + n];                       \
            bf[1] = Bv[(ks * 8 + 4 + (lane & 3)) * VB_ST + n];                   \
            mma8(acc[ni], af, bf);                                               \
        }                                                                        \
    } } while (0)

    V_LOAD(0, 0); CP_COMMIT();
    V_LOAD(32, 1); CP_COMMIT();
    int st = 0;
    for (int c = 0; c < NC; c++) {
        CP_WAIT(1);
        __syncthreads();
        V_COMP(st);
        int s2 = st + 2; if (s2 >= 3) s2 -= 3;
        if (c + 2 < NC) V_LOAD((c + 2) * 32, s2);
        CP_COMMIT();
        st++; if (st >= 3) st = 0;
    }

#pragma unroll
    for (int ni = 0; ni < 8; ni++) {
        int row = rowStart + warp * 16 + (lane >> 2);
        int col = h * HD + ni * 8 + (lane & 3) * 2;
        float* o0 = &Am[((size_t)b * SS + row) * DD + col];
        float* o1 = &Am[((size_t)b * SS + row + 8) * DD + col];
        o0[0] = __uint_as_float(f2tf(acc[ni][0]));
        o0[1] = __uint_as_float(f2tf(acc[ni][1]));
        o1[0] = __uint_as_float(f2tf(acc[ni][2]));
        o1[1] = __uint_as_float(f2tf(acc[ni][3]));
    }
}

// ---------------------------------------------------------------------------
extern "C" void kernel_launch(void* const* d_in, const int* in_sizes, int n_in,
                              void* d_out, int out_size)
{
    const float* x      = (const float*)d_in[0];   // [4,1024,1024]
    const float* mask   = (const float*)d_in[1];   // [4,1,1,1024]
    const float* w_attn = (const float*)d_in[2];   // [1024,3072]
    const float* b_attn = (const float*)d_in[3];   // [1,3072]
    const float* w_proj = (const float*)d_in[4];   // [1024,1024]
    const float* b_proj = (const float*)d_in[5];   // [1,1024]

    float* out = (float*)d_out;
    float* a_out = out;                                  // [4,1024,1024]
    float* w_out = out + (size_t)BB * SS * DD;           // [4,16,1024,1024]

    float *qkv, *am, *xtf, *watf, *wptf;
    cudaGetSymbolAddress((void**)&qkv, g_qkv);
    cudaGetSymbolAddress((void**)&am, g_am);
    cudaGetSymbolAddress((void**)&xtf, g_xtf);
    cudaGetSymbolAddress((void**)&watf, g_watf);
    cudaGetSymbolAddress((void**)&wptf, g_wptf);

    cudaFuncSetAttribute(gemm_tc<true>,
                         cudaFuncAttributeMaxDynamicSharedMemorySize, G_SMEM);
    cudaFuncSetAttribute(gemm_tc<false>,
                         cudaFuncAttributeMaxDynamicSharedMemorySize, G_SMEM);
    cudaFuncSetAttribute(qksm_tc,
                         cudaFuncAttributeMaxDynamicSharedMemorySize, F_SMEM);
    cudaFuncSetAttribute(av_tc,
                         cudaFuncAttributeMaxDynamicSharedMemorySize, V_SMEM);

    // 0) pre-convert inputs to tf32 bit patterns
    cvt_tf32<<<(BB * SS * DD) / 1024, 256>>>(x, xtf);
    cvt_tf32<<<(DD * 3 * DD) / 1024, 256>>>(w_attn, watf);
    cvt_tf32<<<(DD * DD) / 1024, 256>>>(w_proj, wptf);

    // 1) qkv = x @ w_attn + b_attn (rounded to tf32 on write)
    {
        dim3 grid(3 * DD / 128, BB * SS / 128);
        gemm_tc<true><<<grid, 256, G_SMEM>>>(xtf, watf, b_attn, qkv,
                                             DD, DD, 3 * DD, 3 * DD);
    }
    // 2) fused scores + softmax (causal-skip) -> tf32-rounded probs in w_out
    {
        dim3 grid(SS / 16, BB * HH);
        qksm_tc<<<grid, 256, F_SMEM>>>(qkv, mask, w_out);
    }
    // 3) a_heads = W @ V (causal-skip) -> merged g_am (rounded)
    {
        dim3 grid(SS / 128, BB * HH);
        av_tc<<<grid, 256, V_SMEM>>>(w_out, qkv, am);
    }
    // 4) a = am @ w_proj + b_proj -> a_out (exact)
    {
        dim3 grid(DD / 128, BB * SS / 128);
        gemm_tc<false><<<grid, 256, G_SMEM>>>(am, wptf, b_proj, a_out,
                                              DD, DD, DD, DD);
    }
}